// round 12
// baseline (speedup 1.0000x reference)
#include <cuda_runtime.h>
#include <cuda_fp16.h>
#include <cstdint>

// NonLocalLoss: B=4, C=64, N=4096, two branches sharing weights.
// out[b,c] = mean_n x + (fsg_w @ q)/N + fsg_b ; q[c] = (sum_n g[c,n]*E_n)/Z
// E_n = sum_m 2^(F'_nm), F' = (log2e*s)^T f  (flat softmax, shift-invariant).
// F' via single-product fp16 mma.sync (sm_100-safe; measured rel_err ~1e-6).

#define N_SP 4096
#define N_C  64
#define N_BB 8

// s in [n][c] fp16 (A operand, loaded to regs once per CTA)
__device__ __half g_s_h[(size_t)N_BB * N_SP * N_C];
// f fused fragment layout: per row n, 128 B; group (kb,t) at (kb*4+t)*8:
//   bytes 0-3: fp16 k=16kb+2t,2t+1 | bytes 4-7: fp16 k=16kb+8+2t,+1
__device__ uint8_t g_f_fused[(size_t)N_BB * N_SP * 128];
__device__ float g_g[(size_t)N_BB * N_C * N_SP];   // fp32 [C][N]
__device__ float g_rowE[N_BB * N_SP];
__device__ float g_q[N_BB * N_C];
__device__ float g_sumx_part[N_BB * 32 * N_C];     // per-(bb, ntile, c) partial sums

// ---------------------------------------------------------------------------
// prep: s,f,g = conv1x1(x); also emits per-tile x partial sums (fused sumx).
// s scaled by log2e -> [n][c] fp16; f -> fused fp16 fragments; g -> fp32 [C][N].
// ---------------------------------------------------------------------------
__global__ __launch_bounds__(256) void prep_kernel(
    const float* __restrict__ student, const float* __restrict__ teacher,
    const float* __restrict__ si_w, const float* __restrict__ si_b,
    const float* __restrict__ fi_w, const float* __restrict__ fi_b,
    const float* __restrict__ gi_w, const float* __restrict__ gi_b)
{
    extern __shared__ float sm[];
    float* sX = sm;                    // [64][128]
    float* sW = sm + 8192;             // [3][64][64]
    float* sB = sm + 8192 + 12288;     // [3][64]
    const int tid = threadIdx.x;
    const int ntile = blockIdx.x, bb = blockIdx.y;
    const float* x = (bb < 4 ? student : teacher) + (size_t)(bb & 3) * N_C * N_SP;
    const int nbase = ntile * 128;
    const float LOG2E = 1.4426950408889634f;

    for (int i = tid; i < 8192; i += 256) {
        int c = i >> 7, j = i & 127;
        sX[i] = x[(size_t)c * N_SP + nbase + j];
    }
    for (int i = tid; i < 4096; i += 256) {
        sW[i]        = si_w[i] * LOG2E;
        sW[4096 + i] = fi_w[i];
        sW[8192 + i] = gi_w[i];
    }
    if (tid < 64) {
        sB[tid]       = si_b[tid] * LOG2E;
        sB[64 + tid]  = fi_b[tid];
        sB[128 + tid] = gi_b[tid];
    }
    __syncthreads();

    // fused sumx: thread (c = tid>>2, seg = tid&3) sums 32 n's; 4-lane combine.
    {
        const int c = tid >> 2, seg = tid & 3;
        const float* row = sX + c * 128 + seg * 32;
        float s = 0.f;
        #pragma unroll 8
        for (int i = 0; i < 32; ++i) s += row[i];
        s += __shfl_xor_sync(0xffffffffu, s, 1);
        s += __shfl_xor_sync(0xffffffffu, s, 2);
        if (seg == 0) g_sumx_part[(bb * 32 + ntile) * N_C + c] = s;
    }

    const int d0 = (tid >> 4) * 4, n0v = (tid & 15) * 4;
    #pragma unroll
    for (int mat = 0; mat < 3; ++mat) {
        const float* W = sW + mat * 4096;
        float acc[4][8];
        #pragma unroll
        for (int i = 0; i < 4; ++i)
            #pragma unroll
            for (int j = 0; j < 8; ++j) acc[i][j] = 0.f;

        #pragma unroll 4
        for (int k4 = 0; k4 < 16; ++k4) {
            // one float4 per weight row per 4-k chunk (vectorized weight loads)
            float4 wv[4];
            #pragma unroll
            for (int i = 0; i < 4; ++i)
                wv[i] = *(const float4*)&W[(d0 + i) * 64 + k4 * 4];
            #pragma unroll
            for (int kk = 0; kk < 4; ++kk) {
                const int k = k4 * 4 + kk;
                float4 x0 = *(const float4*)&sX[k * 128 + n0v];
                float4 x1 = *(const float4*)&sX[k * 128 + n0v + 64];
                float xv[8] = {x0.x, x0.y, x0.z, x0.w, x1.x, x1.y, x1.z, x1.w};
                #pragma unroll
                for (int i = 0; i < 4; ++i) {
                    const float wvi = ((const float*)&wv[i])[kk];
                    #pragma unroll
                    for (int j = 0; j < 8; ++j) acc[i][j] = fmaf(wvi, xv[j], acc[i][j]);
                }
            }
        }
        if (mat == 0) {
            // s: fp16, [n][c] layout
            __half* outH = g_s_h + (size_t)bb * N_SP * N_C;
            #pragma unroll
            for (int j = 0; j < 8; ++j) {
                int n = nbase + n0v + (j < 4 ? j : 60 + j);
                __half h0 = __float2half_rn(acc[0][j] + sB[d0 + 0]);
                __half h1 = __float2half_rn(acc[1][j] + sB[d0 + 1]);
                __half h2 = __float2half_rn(acc[2][j] + sB[d0 + 2]);
                __half h3 = __float2half_rn(acc[3][j] + sB[d0 + 3]);
                unsigned hi01 = (unsigned)__half_as_ushort(h0) | ((unsigned)__half_as_ushort(h1) << 16);
                unsigned hi23 = (unsigned)__half_as_ushort(h2) | ((unsigned)__half_as_ushort(h3) << 16);
                *(uint2*)&outH[(size_t)n * N_C + d0] = make_uint2(hi01, hi23);
            }
        } else if (mat == 1) {
            // f: fp16, fused mma-fragment layout (128 B per row)
            #pragma unroll
            for (int j = 0; j < 8; ++j) {
                int n = nbase + n0v + (j < 4 ? j : 60 + j);
                __half h0 = __float2half_rn(acc[0][j] + sB[64 + d0 + 0]);
                __half h1 = __float2half_rn(acc[1][j] + sB[64 + d0 + 1]);
                __half h2 = __float2half_rn(acc[2][j] + sB[64 + d0 + 2]);
                __half h3 = __float2half_rn(acc[3][j] + sB[64 + d0 + 3]);
                unsigned p01 = (unsigned)__half_as_ushort(h0) | ((unsigned)__half_as_ushort(h1) << 16);
                unsigned p23 = (unsigned)__half_as_ushort(h2) | ((unsigned)__half_as_ushort(h3) << 16);
                uint8_t* fF = g_f_fused + (size_t)bb * N_SP * 128 + (size_t)n * 128;
                const int kb  = d0 >> 4;
                const int w0  = d0 & 15;
                const int tt0 = (w0 & 7) >> 1;       // pair0 -> t=tt0, pair1 -> t=tt0+1
                const int hi4 = (w0 & 8) ? 4 : 0;    // second k-octet slot
                *(unsigned*)(fF + (kb * 4 + tt0) * 8 + hi4)     = p01;
                *(unsigned*)(fF + (kb * 4 + tt0 + 1) * 8 + hi4) = p23;
            }
        } else {
            float* out = g_g + (size_t)bb * N_C * N_SP;
            #pragma unroll
            for (int i = 0; i < 4; ++i) {
                float bias = sB[128 + d0 + i];
                float4 o0 = make_float4(acc[i][0] + bias, acc[i][1] + bias, acc[i][2] + bias, acc[i][3] + bias);
                float4 o1 = make_float4(acc[i][4] + bias, acc[i][5] + bias, acc[i][6] + bias, acc[i][7] + bias);
                *(float4*)&out[(size_t)(d0 + i) * N_SP + nbase + n0v]      = o0;
                *(float4*)&out[(size_t)(d0 + i) * N_SP + nbase + n0v + 64] = o1;
            }
        }
    }
}

// ---------------------------------------------------------------------------
// attn helpers
// ---------------------------------------------------------------------------
__device__ __forceinline__ uint32_t smem_u32(const void* p) {
    uint32_t a;
    asm("{ .reg .u64 t; cvta.to.shared.u64 t, %1; cvt.u32.u64 %0, t; }" : "=r"(a) : "l"(p));
    return a;
}
__device__ __forceinline__ void cp_async16s(uint32_t dst, const void* src) {
    asm volatile("cp.async.cg.shared.global [%0], [%1], 16;" :: "r"(dst), "l"(src) : "memory");
}
__device__ __forceinline__ float ex2f(float x) {
    float r; asm("ex2.approx.ftz.f32 %0, %1;" : "=f"(r) : "f"(x)); return r;
}
#define MMAF16(c, a, b0, b1) \
    asm volatile("mma.sync.aligned.m16n8k16.row.col.f32.f16.f16.f32 " \
        "{%0,%1,%2,%3}, {%4,%5,%6,%7}, {%8,%9}, {%0,%1,%2,%3};" \
        : "+f"((c)[0]), "+f"((c)[1]), "+f"((c)[2]), "+f"((c)[3]) \
        : "r"((a)[0]), "r"((a)[1]), "r"((a)[2]), "r"((a)[3]), "r"(b0), "r"(b1))

// B tile smem: 128 rows x 160 B (128 data + 32 pad). LDS.64 lane map:
// bankpair = (4g + t) mod 16 -> distinct per 16-lane phase => conflict-free.
#define B_ROWSTR 160
#define B_BUF    (128 * B_ROWSTR)          // 20480 B

// ---------------------------------------------------------------------------
// attn: per warp 32 rows (2 m16 blocks; A fp16 resident in regs).
// Per (nt,kb): 1 LDS.64 -> {b0,b1} feeds 2 mmas (2 row-blocks, 1 product).
// grid (16 rowtiles, 8 bb) = 128 CTAs, 256 thr, smem 40960B, 1 wave.
// ---------------------------------------------------------------------------
__global__ __launch_bounds__(256, 1) void attn_kernel()
{
    extern __shared__ char rawsm[];
    const uint32_t base = smem_u32(rawsm);
    const int tid = threadIdx.x;
    const int wid = tid >> 5, lane = tid & 31;
    const int g = lane >> 2, t = lane & 3;
    const int rowtile = blockIdx.x, bb = blockIdx.y;
    const int rbase = rowtile * 256;
    const __half* SH = g_s_h + (size_t)bb * N_SP * N_C;
    const uint8_t* FF = g_f_fused + (size_t)bb * N_SP * 128;

    // A fragments: 2 row-blocks x 4 kb x 4 regs (resident)
    uint32_t aH[2][4][4];
    {
        const int r0 = rbase + 32 * wid + g;
        #pragma unroll
        for (int rb = 0; rb < 2; ++rb) {
            const int ra = r0 + 16 * rb, rbot = ra + 8;
            #pragma unroll
            for (int kb = 0; kb < 4; ++kb) {
                const int k0 = 16 * kb + 2 * t;
                aH[rb][kb][0] = *(const uint32_t*)&SH[(size_t)ra * N_C + k0];
                aH[rb][kb][1] = *(const uint32_t*)&SH[(size_t)rbot * N_C + k0];
                aH[rb][kb][2] = *(const uint32_t*)&SH[(size_t)ra * N_C + k0 + 8];
                aH[rb][kb][3] = *(const uint32_t*)&SH[(size_t)rbot * N_C + k0 + 8];
            }
        }
    }

    // prefetch B col-tiles 0 and 1 (128 rows x 128 B each)
    #pragma unroll
    for (int p = 0; p < 2; ++p) {
        #pragma unroll
        for (int i = 0; i < 4; ++i) {
            int ci = tid + i * 256;                 // 0..1023
            int row = ci >> 3, ch = ci & 7;
            cp_async16s(base + p * B_BUF + row * B_ROWSTR + ch * 16,
                        FF + (size_t)(p * 128 + row) * 128 + ch * 16);
        }
        asm volatile("cp.async.commit_group;" ::: "memory");
    }

    float e00 = 0.f, e01 = 0.f, e10 = 0.f, e11 = 0.f;

    for (int j = 0; j < 32; ++j) {
        asm volatile("cp.async.wait_group 1;" ::: "memory");
        __syncthreads();                            // tile j ready for all warps

        const char* buf = rawsm + (j & 1) * B_BUF;

        #pragma unroll 2
        for (int nt = 0; nt < 16; ++nt) {
            const char* rowp = buf + (nt * 8 + g) * B_ROWSTR + t * 8;
            uint2 bv[4];
            #pragma unroll
            for (int kb = 0; kb < 4; ++kb)
                bv[kb] = *(const uint2*)(rowp + kb * 32);

            float cA0[4] = {0.f,0.f,0.f,0.f};
            float cA1[4] = {0.f,0.f,0.f,0.f};
            #pragma unroll
            for (int kb = 0; kb < 4; ++kb) {
                MMAF16(cA0, aH[0][kb], bv[kb].x, bv[kb].y);
                MMAF16(cA1, aH[1][kb], bv[kb].x, bv[kb].y);
            }
            e00 += ex2f(cA0[0]) + ex2f(cA0[1]);
            e01 += ex2f(cA0[2]) + ex2f(cA0[3]);
            e10 += ex2f(cA1[0]) + ex2f(cA1[1]);
            e11 += ex2f(cA1[2]) + ex2f(cA1[3]);
        }

        __syncthreads();                            // all warps done with buffer j
        if (j + 2 < 32) {
            const int cb = (j + 2) * 128;
            #pragma unroll
            for (int i = 0; i < 4; ++i) {
                int ci = tid + i * 256;
                int row = ci >> 3, ch = ci & 7;
                cp_async16s(base + (j & 1) * B_BUF + row * B_ROWSTR + ch * 16,
                            FF + (size_t)(cb + row) * 128 + ch * 16);
            }
            asm volatile("cp.async.commit_group;" ::: "memory");
        }
    }

    // reduce over the 4 lanes (t) sharing each row
    #pragma unroll
    for (int off = 1; off < 4; off <<= 1) {
        e00 += __shfl_xor_sync(0xffffffffu, e00, off);
        e01 += __shfl_xor_sync(0xffffffffu, e01, off);
        e10 += __shfl_xor_sync(0xffffffffu, e10, off);
        e11 += __shfl_xor_sync(0xffffffffu, e11, off);
    }
    if (t == 0) {
        const int rb0 = bb * N_SP + rbase + 32 * wid + g;
        g_rowE[rb0]      = e00;
        g_rowE[rb0 + 8]  = e01;
        g_rowE[rb0 + 16] = e10;
        g_rowE[rb0 + 24] = e11;
    }
}

// ---------------------------------------------------------------------------
// qdot: one CTA per (bb,c): q = (sum_n g[c,n]*E_n) / (sum_n E_n). grid 512.
// ---------------------------------------------------------------------------
__global__ __launch_bounds__(128) void qdot_kernel()
{
    __shared__ float redP[4], redZ[4];
    const int tid = threadIdx.x;
    const int blk = blockIdx.x;
    const int bb = blk >> 6, c = blk & 63;
    const float4* gp = (const float4*)(g_g + (size_t)bb * N_C * N_SP + (size_t)c * N_SP);
    const float4* ep = (const float4*)(g_rowE + bb * N_SP);
    float p = 0.f, z = 0.f;
    #pragma unroll 2
    for (int i = tid; i < 1024; i += 128) {
        float4 a = gp[i], e = ep[i];
        p = fmaf(a.x, e.x, p); p = fmaf(a.y, e.y, p);
        p = fmaf(a.z, e.z, p); p = fmaf(a.w, e.w, p);
        z += (e.x + e.y) + (e.z + e.w);
    }
    #pragma unroll
    for (int off = 16; off > 0; off >>= 1) {
        p += __shfl_xor_sync(0xffffffffu, p, off);
        z += __shfl_xor_sync(0xffffffffu, z, off);
    }
    if ((tid & 31) == 0) { redP[tid >> 5] = p; redZ[tid >> 5] = z; }
    __syncthreads();
    if (tid == 0) {
        float P = redP[0] + redP[1] + redP[2] + redP[3];
        float Z = redZ[0] + redZ[1] + redZ[2] + redZ[3];
        g_q[bb * 64 + c] = P / Z;
    }
}

// ---------------------------------------------------------------------------
// loss: out[b,c] per branch (folding sumx partials), MSE-sum, scale.
// ---------------------------------------------------------------------------
__global__ __launch_bounds__(256) void loss_kernel(const float* __restrict__ fsg_w,
                                                   const float* __restrict__ fsg_b,
                                                   float* __restrict__ out, int out_size)
{
    __shared__ float red[256];
    const int tid = threadIdx.x;
    const int b = tid >> 6, d = tid & 63;
    float dot_s = 0.f, dot_t = 0.f;
    #pragma unroll 8
    for (int c = 0; c < 64; ++c) {
        float w = fsg_w[d * 64 + c];
        dot_s = fmaf(w, g_q[b * 64 + c], dot_s);
        dot_t = fmaf(w, g_q[(4 + b) * 64 + c], dot_t);
    }
    float sx_s = 0.f, sx_t = 0.f;
    #pragma unroll 8
    for (int p = 0; p < 32; ++p) {
        sx_s += g_sumx_part[(b * 32 + p) * N_C + d];
        sx_t += g_sumx_part[((4 + b) * 32 + p) * N_C + d];
    }
    const float invN = 1.f / 4096.f;
    float out_s = sx_s * invN + dot_s * invN + fsg_b[d];
    float out_t = sx_t * invN + dot_t * invN + fsg_b[d];
    float diff = out_s - out_t;
    red[tid] = diff * diff;
    __syncthreads();
    for (int off = 128; off > 0; off >>= 1) {
        if (tid < off) red[tid] += red[tid + off];
        __syncthreads();
    }
    const float nlB = 0.05f * 4e-4f * red[0];        // non_loss * B
    for (int i = tid; i < out_size; i += 256)
        out[i] = (i == 0) ? nlB : nlB * 0.25f;       // [non_loss*B, non_loss]
}

// ---------------------------------------------------------------------------
extern "C" void kernel_launch(void* const* d_in, const int* in_sizes, int n_in,
                              void* d_out, int out_size)
{
    (void)in_sizes; (void)n_in;
    const float* student = (const float*)d_in[0];
    const float* teacher = (const float*)d_in[1];
    const float* si_w  = (const float*)d_in[2];
    const float* si_b  = (const float*)d_in[3];
    const float* fi_w  = (const float*)d_in[4];
    const float* fi_b  = (const float*)d_in[5];
    const float* gi_w  = (const float*)d_in[6];
    const float* gi_b  = (const float*)d_in[7];
    const float* fsg_w = (const float*)d_in[8];
    const float* fsg_b = (const float*)d_in[9];

    cudaFuncSetAttribute(prep_kernel, cudaFuncAttributeMaxDynamicSharedMemorySize, 82688);
    cudaFuncSetAttribute(attn_kernel, cudaFuncAttributeMaxDynamicSharedMemorySize, 2 * B_BUF);

    prep_kernel<<<dim3(32, 8), 256, 82688>>>(student, teacher, si_w, si_b, fi_w, fi_b, gi_w, gi_b);
    attn_kernel<<<dim3(16, 8), 256, 2 * B_BUF>>>();
    qdot_kernel<<<512, 128>>>();
    loss_kernel<<<1, 256>>>(fsg_w, fsg_b, (float*)d_out, out_size);
}

// round 13
// speedup vs baseline: 1.0978x; 1.0978x over previous
#include <cuda_runtime.h>
#include <cuda_fp16.h>
#include <cstdint>

// NonLocalLoss: B=4, C=64, N=4096, two branches sharing weights.
// out[b,c] = mean_n x + (fsg_w @ q)/N + fsg_b ; q[c] = (sum_n g[c,n]*E_n)/Z
// E_n = sum_m 2^(F'_nm), F' = (log2e*s)^T f  (flat softmax, shift-invariant).
// F' via single-product fp16 mma.sync (sm_100-safe; measured rel_err ~1e-6).

#define N_SP 4096
#define N_C  64
#define N_BB 8

// s in [n][c] fp16 (A operand, loaded to regs once per CTA)
__device__ __half g_s_h[(size_t)N_BB * N_SP * N_C];
// f fused fragment layout: per row n, 128 B; group (kb,t) at (kb*4+t)*8:
//   bytes 0-3: fp16 k=16kb+2t,2t+1 | bytes 4-7: fp16 k=16kb+8+2t,+1
__device__ uint8_t g_f_fused[(size_t)N_BB * N_SP * 128];
__device__ float g_g[(size_t)N_BB * N_C * N_SP];   // fp32 [C][N]
__device__ float g_rowE[N_BB * N_SP];
__device__ float g_q[N_BB * N_C];
__device__ float g_sumx_part[N_BB * 32 * N_C];     // per-(bb, ntile, c) partials
__device__ float g_sumx[N_BB * N_C];               // folded by qdot

// ---------------------------------------------------------------------------
// prep: s,f,g = conv1x1(x); also emits per-tile x partial sums (fused sumx).
// s scaled by log2e -> [n][c] fp16; f -> fused fp16 fragments; g -> fp32 [C][N].
// ---------------------------------------------------------------------------
__global__ __launch_bounds__(256) void prep_kernel(
    const float* __restrict__ student, const float* __restrict__ teacher,
    const float* __restrict__ si_w, const float* __restrict__ si_b,
    const float* __restrict__ fi_w, const float* __restrict__ fi_b,
    const float* __restrict__ gi_w, const float* __restrict__ gi_b)
{
    extern __shared__ float sm[];
    float* sX = sm;                    // [64][128]
    float* sW = sm + 8192;             // [3][64][64]
    float* sB = sm + 8192 + 12288;     // [3][64]
    const int tid = threadIdx.x;
    const int ntile = blockIdx.x, bb = blockIdx.y;
    const float* x = (bb < 4 ? student : teacher) + (size_t)(bb & 3) * N_C * N_SP;
    const int nbase = ntile * 128;
    const float LOG2E = 1.4426950408889634f;

    for (int i = tid; i < 8192; i += 256) {
        int c = i >> 7, j = i & 127;
        sX[i] = x[(size_t)c * N_SP + nbase + j];
    }
    for (int i = tid; i < 4096; i += 256) {
        sW[i]        = si_w[i] * LOG2E;
        sW[4096 + i] = fi_w[i];
        sW[8192 + i] = gi_w[i];
    }
    if (tid < 64) {
        sB[tid]       = si_b[tid] * LOG2E;
        sB[64 + tid]  = fi_b[tid];
        sB[128 + tid] = gi_b[tid];
    }
    __syncthreads();

    // fused sumx: thread (c = tid>>2, seg = tid&3) sums 32 n's; 4-lane combine.
    {
        const int c = tid >> 2, seg = tid & 3;
        const float* row = sX + c * 128 + seg * 32;
        float s = 0.f;
        #pragma unroll 8
        for (int i = 0; i < 32; ++i) s += row[i];
        s += __shfl_xor_sync(0xffffffffu, s, 1);
        s += __shfl_xor_sync(0xffffffffu, s, 2);
        if (seg == 0) g_sumx_part[(bb * 32 + ntile) * N_C + c] = s;
    }

    const int d0 = (tid >> 4) * 4, n0v = (tid & 15) * 4;
    #pragma unroll
    for (int mat = 0; mat < 3; ++mat) {
        const float* W = sW + mat * 4096;
        float acc[4][8];
        #pragma unroll
        for (int i = 0; i < 4; ++i)
            #pragma unroll
            for (int j = 0; j < 8; ++j) acc[i][j] = 0.f;

        #pragma unroll 4
        for (int k4 = 0; k4 < 16; ++k4) {
            float4 wv[4];
            #pragma unroll
            for (int i = 0; i < 4; ++i)
                wv[i] = *(const float4*)&W[(d0 + i) * 64 + k4 * 4];
            #pragma unroll
            for (int kk = 0; kk < 4; ++kk) {
                const int k = k4 * 4 + kk;
                float4 x0 = *(const float4*)&sX[k * 128 + n0v];
                float4 x1 = *(const float4*)&sX[k * 128 + n0v + 64];
                float xv[8] = {x0.x, x0.y, x0.z, x0.w, x1.x, x1.y, x1.z, x1.w};
                #pragma unroll
                for (int i = 0; i < 4; ++i) {
                    const float wvi = ((const float*)&wv[i])[kk];
                    #pragma unroll
                    for (int j = 0; j < 8; ++j) acc[i][j] = fmaf(wvi, xv[j], acc[i][j]);
                }
            }
        }
        if (mat == 0) {
            __half* outH = g_s_h + (size_t)bb * N_SP * N_C;
            #pragma unroll
            for (int j = 0; j < 8; ++j) {
                int n = nbase + n0v + (j < 4 ? j : 60 + j);
                __half h0 = __float2half_rn(acc[0][j] + sB[d0 + 0]);
                __half h1 = __float2half_rn(acc[1][j] + sB[d0 + 1]);
                __half h2 = __float2half_rn(acc[2][j] + sB[d0 + 2]);
                __half h3 = __float2half_rn(acc[3][j] + sB[d0 + 3]);
                unsigned hi01 = (unsigned)__half_as_ushort(h0) | ((unsigned)__half_as_ushort(h1) << 16);
                unsigned hi23 = (unsigned)__half_as_ushort(h2) | ((unsigned)__half_as_ushort(h3) << 16);
                *(uint2*)&outH[(size_t)n * N_C + d0] = make_uint2(hi01, hi23);
            }
        } else if (mat == 1) {
            #pragma unroll
            for (int j = 0; j < 8; ++j) {
                int n = nbase + n0v + (j < 4 ? j : 60 + j);
                __half h0 = __float2half_rn(acc[0][j] + sB[64 + d0 + 0]);
                __half h1 = __float2half_rn(acc[1][j] + sB[64 + d0 + 1]);
                __half h2 = __float2half_rn(acc[2][j] + sB[64 + d0 + 2]);
                __half h3 = __float2half_rn(acc[3][j] + sB[64 + d0 + 3]);
                unsigned p01 = (unsigned)__half_as_ushort(h0) | ((unsigned)__half_as_ushort(h1) << 16);
                unsigned p23 = (unsigned)__half_as_ushort(h2) | ((unsigned)__half_as_ushort(h3) << 16);
                uint8_t* fF = g_f_fused + (size_t)bb * N_SP * 128 + (size_t)n * 128;
                const int kb  = d0 >> 4;
                const int w0  = d0 & 15;
                const int tt0 = (w0 & 7) >> 1;
                const int hi4 = (w0 & 8) ? 4 : 0;
                *(unsigned*)(fF + (kb * 4 + tt0) * 8 + hi4)     = p01;
                *(unsigned*)(fF + (kb * 4 + tt0 + 1) * 8 + hi4) = p23;
            }
        } else {
            float* out = g_g + (size_t)bb * N_C * N_SP;
            #pragma unroll
            for (int i = 0; i < 4; ++i) {
                float bias = sB[128 + d0 + i];
                float4 o0 = make_float4(acc[i][0] + bias, acc[i][1] + bias, acc[i][2] + bias, acc[i][3] + bias);
                float4 o1 = make_float4(acc[i][4] + bias, acc[i][5] + bias, acc[i][6] + bias, acc[i][7] + bias);
                *(float4*)&out[(size_t)(d0 + i) * N_SP + nbase + n0v]      = o0;
                *(float4*)&out[(size_t)(d0 + i) * N_SP + nbase + n0v + 64] = o1;
            }
        }
    }
}

// ---------------------------------------------------------------------------
// attn helpers
// ---------------------------------------------------------------------------
__device__ __forceinline__ uint32_t smem_u32(const void* p) {
    uint32_t a;
    asm("{ .reg .u64 t; cvta.to.shared.u64 t, %1; cvt.u32.u64 %0, t; }" : "=r"(a) : "l"(p));
    return a;
}
__device__ __forceinline__ void cp_async16s(uint32_t dst, const void* src) {
    asm volatile("cp.async.cg.shared.global [%0], [%1], 16;" :: "r"(dst), "l"(src) : "memory");
}
__device__ __forceinline__ float ex2f(float x) {
    float r; asm("ex2.approx.ftz.f32 %0, %1;" : "=f"(r) : "f"(x)); return r;
}
#define MMAF16(c, a, b0, b1) \
    asm volatile("mma.sync.aligned.m16n8k16.row.col.f32.f16.f16.f32 " \
        "{%0,%1,%2,%3}, {%4,%5,%6,%7}, {%8,%9}, {%0,%1,%2,%3};" \
        : "+f"((c)[0]), "+f"((c)[1]), "+f"((c)[2]), "+f"((c)[3]) \
        : "r"((a)[0]), "r"((a)[1]), "r"((a)[2]), "r"((a)[3]), "r"(b0), "r"(b1))

#define B_ROWSTR 160
#define B_BUF    (128 * B_ROWSTR)          // 20480 B

// ---------------------------------------------------------------------------
// attn: per warp 32 rows (2 m16 blocks; A fp16 resident in regs).
// grid (16 rowtiles, 8 bb) = 128 CTAs, 256 thr, smem 40960B, 1 wave.
// ---------------------------------------------------------------------------
__global__ __launch_bounds__(256, 1) void attn_kernel()
{
    extern __shared__ char rawsm[];
    const uint32_t base = smem_u32(rawsm);
    const int tid = threadIdx.x;
    const int wid = tid >> 5, lane = tid & 31;
    const int g = lane >> 2, t = lane & 3;
    const int rowtile = blockIdx.x, bb = blockIdx.y;
    const int rbase = rowtile * 256;
    const __half* SH = g_s_h + (size_t)bb * N_SP * N_C;
    const uint8_t* FF = g_f_fused + (size_t)bb * N_SP * 128;

    uint32_t aH[2][4][4];
    {
        const int r0 = rbase + 32 * wid + g;
        #pragma unroll
        for (int rb = 0; rb < 2; ++rb) {
            const int ra = r0 + 16 * rb, rbot = ra + 8;
            #pragma unroll
            for (int kb = 0; kb < 4; ++kb) {
                const int k0 = 16 * kb + 2 * t;
                aH[rb][kb][0] = *(const uint32_t*)&SH[(size_t)ra * N_C + k0];
                aH[rb][kb][1] = *(const uint32_t*)&SH[(size_t)rbot * N_C + k0];
                aH[rb][kb][2] = *(const uint32_t*)&SH[(size_t)ra * N_C + k0 + 8];
                aH[rb][kb][3] = *(const uint32_t*)&SH[(size_t)rbot * N_C + k0 + 8];
            }
        }
    }

    #pragma unroll
    for (int p = 0; p < 2; ++p) {
        #pragma unroll
        for (int i = 0; i < 4; ++i) {
            int ci = tid + i * 256;
            int row = ci >> 3, ch = ci & 7;
            cp_async16s(base + p * B_BUF + row * B_ROWSTR + ch * 16,
                        FF + (size_t)(p * 128 + row) * 128 + ch * 16);
        }
        asm volatile("cp.async.commit_group;" ::: "memory");
    }

    float e00 = 0.f, e01 = 0.f, e10 = 0.f, e11 = 0.f;

    for (int j = 0; j < 32; ++j) {
        asm volatile("cp.async.wait_group 1;" ::: "memory");
        __syncthreads();

        const char* buf = rawsm + (j & 1) * B_BUF;

        #pragma unroll 2
        for (int nt = 0; nt < 16; ++nt) {
            const char* rowp = buf + (nt * 8 + g) * B_ROWSTR + t * 8;
            uint2 bv[4];
            #pragma unroll
            for (int kb = 0; kb < 4; ++kb)
                bv[kb] = *(const uint2*)(rowp + kb * 32);

            float cA0[4] = {0.f,0.f,0.f,0.f};
            float cA1[4] = {0.f,0.f,0.f,0.f};
            #pragma unroll
            for (int kb = 0; kb < 4; ++kb) {
                MMAF16(cA0, aH[0][kb], bv[kb].x, bv[kb].y);
                MMAF16(cA1, aH[1][kb], bv[kb].x, bv[kb].y);
            }
            e00 += ex2f(cA0[0]) + ex2f(cA0[1]);
            e01 += ex2f(cA0[2]) + ex2f(cA0[3]);
            e10 += ex2f(cA1[0]) + ex2f(cA1[1]);
            e11 += ex2f(cA1[2]) + ex2f(cA1[3]);
        }

        __syncthreads();
        if (j + 2 < 32) {
            const int cb = (j + 2) * 128;
            #pragma unroll
            for (int i = 0; i < 4; ++i) {
                int ci = tid + i * 256;
                int row = ci >> 3, ch = ci & 7;
                cp_async16s(base + (j & 1) * B_BUF + row * B_ROWSTR + ch * 16,
                            FF + (size_t)(cb + row) * 128 + ch * 16);
            }
            asm volatile("cp.async.commit_group;" ::: "memory");
        }
    }

    #pragma unroll
    for (int off = 1; off < 4; off <<= 1) {
        e00 += __shfl_xor_sync(0xffffffffu, e00, off);
        e01 += __shfl_xor_sync(0xffffffffu, e01, off);
        e10 += __shfl_xor_sync(0xffffffffu, e10, off);
        e11 += __shfl_xor_sync(0xffffffffu, e11, off);
    }
    if (t == 0) {
        const int rb0 = bb * N_SP + rbase + 32 * wid + g;
        g_rowE[rb0]      = e00;
        g_rowE[rb0 + 8]  = e01;
        g_rowE[rb0 + 16] = e10;
        g_rowE[rb0 + 24] = e11;
    }
}

// ---------------------------------------------------------------------------
// qdot: one CTA per (bb,c): q = (sum_n g[c,n]*E_n) / (sum_n E_n). grid 512.
// Also folds the 32 sumx partials for (bb,c) -> g_sumx (parallel, hidden).
// ---------------------------------------------------------------------------
__global__ __launch_bounds__(128) void qdot_kernel()
{
    __shared__ float redP[4], redZ[4];
    const int tid = threadIdx.x;
    const int blk = blockIdx.x;
    const int bb = blk >> 6, c = blk & 63;

    // fold sumx partials (first warp; 1 load/lane, warp-reduce)
    if (tid < 32) {
        float s = g_sumx_part[(bb * 32 + tid) * N_C + c];
        #pragma unroll
        for (int off = 16; off > 0; off >>= 1)
            s += __shfl_xor_sync(0xffffffffu, s, off);
        if (tid == 0) g_sumx[bb * N_C + c] = s;
    }

    const float4* gp = (const float4*)(g_g + (size_t)bb * N_C * N_SP + (size_t)c * N_SP);
    const float4* ep = (const float4*)(g_rowE + bb * N_SP);
    float p = 0.f, z = 0.f;
    #pragma unroll 2
    for (int i = tid; i < 1024; i += 128) {
        float4 a = gp[i], e = ep[i];
        p = fmaf(a.x, e.x, p); p = fmaf(a.y, e.y, p);
        p = fmaf(a.z, e.z, p); p = fmaf(a.w, e.w, p);
        z += (e.x + e.y) + (e.z + e.w);
    }
    #pragma unroll
    for (int off = 16; off > 0; off >>= 1) {
        p += __shfl_xor_sync(0xffffffffu, p, off);
        z += __shfl_xor_sync(0xffffffffu, z, off);
    }
    if ((tid & 31) == 0) { redP[tid >> 5] = p; redZ[tid >> 5] = z; }
    __syncthreads();
    if (tid == 0) {
        float P = redP[0] + redP[1] + redP[2] + redP[3];
        float Z = redZ[0] + redZ[1] + redZ[2] + redZ[3];
        g_q[bb * 64 + c] = P / Z;
    }
}

// ---------------------------------------------------------------------------
// loss: cooperative smem preload (coalesced, parallel), then dots from smem.
// fsg_w stored transposed with stride 65 -> conflict-free write AND read.
// ---------------------------------------------------------------------------
__global__ __launch_bounds__(256) void loss_kernel(const float* __restrict__ fsg_w,
                                                   const float* __restrict__ fsg_b,
                                                   float* __restrict__ out, int out_size)
{
    __shared__ float sQ[512];
    __shared__ float sSX[512];
    __shared__ float sWt[64 * 65];     // sWt[c*65+d] = fsg_w[d*64+c]
    __shared__ float red[256];
    const int tid = threadIdx.x;

    #pragma unroll
    for (int i = tid; i < 512; i += 256) {
        sQ[i]  = g_q[i];
        sSX[i] = g_sumx[i];
    }
    #pragma unroll
    for (int i = tid; i < 4096; i += 256) {
        int d = i >> 6, c = i & 63;
        sWt[c * 65 + d] = fsg_w[i];
    }
    __syncthreads();

    const int b = tid >> 6, d = tid & 63;
    float dot_s = 0.f, dot_t = 0.f;
    #pragma unroll 8
    for (int c = 0; c < 64; ++c) {
        float w = sWt[c * 65 + d];
        dot_s = fmaf(w, sQ[b * 64 + c], dot_s);
        dot_t = fmaf(w, sQ[(4 + b) * 64 + c], dot_t);
    }
    const float invN = 1.f / 4096.f;
    float out_s = sSX[b * 64 + d] * invN + dot_s * invN + fsg_b[d];
    float out_t = sSX[(4 + b) * 64 + d] * invN + dot_t * invN + fsg_b[d];
    float diff = out_s - out_t;
    red[tid] = diff * diff;
    __syncthreads();
    for (int off = 128; off > 0; off >>= 1) {
        if (tid < off) red[tid] += red[tid + off];
        __syncthreads();
    }
    const float nlB = 0.05f * 4e-4f * red[0];        // non_loss * B
    for (int i = tid; i < out_size; i += 256)
        out[i] = (i == 0) ? nlB : nlB * 0.25f;       // [non_loss*B, non_loss]
}

// ---------------------------------------------------------------------------
extern "C" void kernel_launch(void* const* d_in, const int* in_sizes, int n_in,
                              void* d_out, int out_size)
{
    (void)in_sizes; (void)n_in;
    const float* student = (const float*)d_in[0];
    const float* teacher = (const float*)d_in[1];
    const float* si_w  = (const float*)d_in[2];
    const float* si_b  = (const float*)d_in[3];
    const float* fi_w  = (const float*)d_in[4];
    const float* fi_b  = (const float*)d_in[5];
    const float* gi_w  = (const float*)d_in[6];
    const float* gi_b  = (const float*)d_in[7];
    const float* fsg_w = (const float*)d_in[8];
    const float* fsg_b = (const float*)d_in[9];

    cudaFuncSetAttribute(prep_kernel, cudaFuncAttributeMaxDynamicSharedMemorySize, 82688);
    cudaFuncSetAttribute(attn_kernel, cudaFuncAttributeMaxDynamicSharedMemorySize, 2 * B_BUF);

    prep_kernel<<<dim3(32, 8), 256, 82688>>>(student, teacher, si_w, si_b, fi_w, fi_b, gi_w, gi_b);
    attn_kernel<<<dim3(16, 8), 256, 2 * B_BUF>>>();
    qdot_kernel<<<512, 128>>>();
    loss_kernel<<<1, 256>>>(fsg_w, fsg_b, (float*)d_out, out_size);
}

// round 15
// speedup vs baseline: 1.0981x; 1.0003x over previous
#include <cuda_runtime.h>
#include <cuda_fp16.h>
#include <cstdint>

// NonLocalLoss: B=4, C=64, N=4096, two branches sharing weights.
// out[b,c] = mean_n x + (fsg_w @ q)/N + fsg_b ; q[c] = (sum_n g[c,n]*E_n)/Z
// E_n = sum_m 2^(F'_nm), F' = (log2e*s)^T f  (flat softmax, shift-invariant).
// F' via single-product fp16 mma.sync (sm_100-safe; measured rel_err ~1e-6).

#define N_SP 4096
#define N_C  64
#define N_BB 8

// s in [n][c] fp16 (A operand, loaded to regs once per CTA)
__device__ __half g_s_h[(size_t)N_BB * N_SP * N_C];
// f fused fragment layout: per row n, 128 B; group (kb,t) at (kb*4+t)*8:
//   bytes 0-3: fp16 k=16kb+2t,2t+1 | bytes 4-7: fp16 k=16kb+8+2t,+1
__device__ uint8_t g_f_fused[(size_t)N_BB * N_SP * 128];
__device__ __half g_g_h[(size_t)N_BB * N_C * N_SP];   // fp16 [C][N]
__device__ float g_rowE[N_BB * N_SP];
__device__ float g_q[N_BB * N_C];
__device__ float g_sumx_part[N_BB * 32 * N_C];        // per-(bb, ntile, c) partials
__device__ float g_sumx[N_BB * N_C];                  // folded by qdot

#define STAGE_ROWB 132                                 // 128 data + 4 pad bytes
#define PREP_SMEM  (82688 + 128 * STAGE_ROWB + 64)     // + stage (aligned slack)

// ---------------------------------------------------------------------------
// prep: s,f,g = conv1x1(x); fused sumx partials. s,f staged through smem for
// coalesced stores (copy-out in 4B words: stride 132 is only 4B-aligned);
// g stored fp16 directly (already coalesced).
// ---------------------------------------------------------------------------
__global__ __launch_bounds__(256) void prep_kernel(
    const float* __restrict__ student, const float* __restrict__ teacher,
    const float* __restrict__ si_w, const float* __restrict__ si_b,
    const float* __restrict__ fi_w, const float* __restrict__ fi_b,
    const float* __restrict__ gi_w, const float* __restrict__ gi_b)
{
    extern __shared__ float sm[];
    float* sX = sm;                    // [64][128]
    float* sW = sm + 8192;             // [3][64][64]
    float* sB = sm + 8192 + 12288;     // [3][64]
    uint8_t* sStage = (uint8_t*)(sm + 8192 + 12288 + 192);   // 128 x 132 B
    const int tid = threadIdx.x;
    const int ntile = blockIdx.x, bb = blockIdx.y;
    const float* x = (bb < 4 ? student : teacher) + (size_t)(bb & 3) * N_C * N_SP;
    const int nbase = ntile * 128;
    const float LOG2E = 1.4426950408889634f;

    for (int i = tid; i < 8192; i += 256) {
        int c = i >> 7, j = i & 127;
        sX[i] = x[(size_t)c * N_SP + nbase + j];
    }
    for (int i = tid; i < 4096; i += 256) {
        sW[i]        = si_w[i] * LOG2E;
        sW[4096 + i] = fi_w[i];
        sW[8192 + i] = gi_w[i];
    }
    if (tid < 64) {
        sB[tid]       = si_b[tid] * LOG2E;
        sB[64 + tid]  = fi_b[tid];
        sB[128 + tid] = gi_b[tid];
    }
    __syncthreads();

    // fused sumx: thread (c = tid>>2, seg = tid&3) sums 32 n's; 4-lane combine.
    {
        const int c = tid >> 2, seg = tid & 3;
        const float* row = sX + c * 128 + seg * 32;
        float s = 0.f;
        #pragma unroll 8
        for (int i = 0; i < 32; ++i) s += row[i];
        s += __shfl_xor_sync(0xffffffffu, s, 1);
        s += __shfl_xor_sync(0xffffffffu, s, 2);
        if (seg == 0) g_sumx_part[(bb * 32 + ntile) * N_C + c] = s;
    }

    const int d0 = (tid >> 4) * 4, n0v = (tid & 15) * 4;
    #pragma unroll
    for (int mat = 0; mat < 3; ++mat) {
        const float* W = sW + mat * 4096;
        float acc[4][8];
        #pragma unroll
        for (int i = 0; i < 4; ++i)
            #pragma unroll
            for (int j = 0; j < 8; ++j) acc[i][j] = 0.f;

        #pragma unroll 4
        for (int k4 = 0; k4 < 16; ++k4) {
            float4 wv[4];
            #pragma unroll
            for (int i = 0; i < 4; ++i)
                wv[i] = *(const float4*)&W[(d0 + i) * 64 + k4 * 4];
            #pragma unroll
            for (int kk = 0; kk < 4; ++kk) {
                const int k = k4 * 4 + kk;
                float4 x0 = *(const float4*)&sX[k * 128 + n0v];
                float4 x1 = *(const float4*)&sX[k * 128 + n0v + 64];
                float xv[8] = {x0.x, x0.y, x0.z, x0.w, x1.x, x1.y, x1.z, x1.w};
                #pragma unroll
                for (int i = 0; i < 4; ++i) {
                    const float wvi = ((const float*)&wv[i])[kk];
                    #pragma unroll
                    for (int j = 0; j < 8; ++j) acc[i][j] = fmaf(wvi, xv[j], acc[i][j]);
                }
            }
        }

        if (mat < 2) {
            // stage fp16 outputs into smem (scattered writes cheap there;
            // 132B stride decorrelates banks, 4B-aligned only)
            #pragma unroll
            for (int j = 0; j < 8; ++j) {
                int row = n0v + (j < 4 ? j : 60 + j);       // 0..127
                __half h0 = __float2half_rn(acc[0][j] + sB[mat * 64 + d0 + 0]);
                __half h1 = __float2half_rn(acc[1][j] + sB[mat * 64 + d0 + 1]);
                __half h2 = __float2half_rn(acc[2][j] + sB[mat * 64 + d0 + 2]);
                __half h3 = __float2half_rn(acc[3][j] + sB[mat * 64 + d0 + 3]);
                unsigned p01 = (unsigned)__half_as_ushort(h0) | ((unsigned)__half_as_ushort(h1) << 16);
                unsigned p23 = (unsigned)__half_as_ushort(h2) | ((unsigned)__half_as_ushort(h3) << 16);
                if (mat == 0) {
                    // s layout within row: halves at col d0..d0+3 (4B stores)
                    *(unsigned*)(sStage + row * STAGE_ROWB + d0 * 2)     = p01;
                    *(unsigned*)(sStage + row * STAGE_ROWB + d0 * 2 + 4) = p23;
                } else {
                    // f fused layout within row
                    const int kb  = d0 >> 4;
                    const int w0  = d0 & 15;
                    const int tt0 = (w0 & 7) >> 1;
                    const int hi4 = (w0 & 8) ? 4 : 0;
                    *(unsigned*)(sStage + row * STAGE_ROWB + (kb * 4 + tt0) * 8 + hi4)     = p01;
                    *(unsigned*)(sStage + row * STAGE_ROWB + (kb * 4 + tt0 + 1) * 8 + hi4) = p23;
                }
            }
            __syncthreads();
            // coalesced copy out: 16 KB in 4B words (alignment-safe for 132B
            // stride), 16 passes x 256 threads x 4B; STG fully coalesced.
            {
                uint8_t* dst = (mat == 0)
                    ? (uint8_t*)(g_s_h + (size_t)bb * N_SP * N_C) + (size_t)nbase * 128
                    : g_f_fused + (size_t)bb * N_SP * 128 + (size_t)nbase * 128;
                #pragma unroll
                for (int pass = 0; pass < 16; ++pass) {
                    int m = pass * 1024 + tid * 4;          // byte index 0..16383
                    int row = m >> 7, off = m & 127;
                    unsigned v = *(const unsigned*)(sStage + row * STAGE_ROWB + off);
                    *(unsigned*)(dst + (size_t)row * 128 + off) = v;
                }
            }
            __syncthreads();   // stage reads done before next mat overwrites
        } else {
            // g: fp16, [C][N], directly coalesced (lanes 0-15 contiguous 8B)
            __half* out = g_g_h + (size_t)bb * N_C * N_SP;
            #pragma unroll
            for (int i = 0; i < 4; ++i) {
                float bias = sB[128 + d0 + i];
                __half a0 = __float2half_rn(acc[i][0] + bias);
                __half a1 = __float2half_rn(acc[i][1] + bias);
                __half a2 = __float2half_rn(acc[i][2] + bias);
                __half a3 = __float2half_rn(acc[i][3] + bias);
                __half b0 = __float2half_rn(acc[i][4] + bias);
                __half b1 = __float2half_rn(acc[i][5] + bias);
                __half b2 = __float2half_rn(acc[i][6] + bias);
                __half b3 = __float2half_rn(acc[i][7] + bias);
                unsigned pa0 = (unsigned)__half_as_ushort(a0) | ((unsigned)__half_as_ushort(a1) << 16);
                unsigned pa1 = (unsigned)__half_as_ushort(a2) | ((unsigned)__half_as_ushort(a3) << 16);
                unsigned pb0 = (unsigned)__half_as_ushort(b0) | ((unsigned)__half_as_ushort(b1) << 16);
                unsigned pb1 = (unsigned)__half_as_ushort(b2) | ((unsigned)__half_as_ushort(b3) << 16);
                *(uint2*)&out[(size_t)(d0 + i) * N_SP + nbase + n0v]      = make_uint2(pa0, pa1);
                *(uint2*)&out[(size_t)(d0 + i) * N_SP + nbase + n0v + 64] = make_uint2(pb0, pb1);
            }
        }
    }
}

// ---------------------------------------------------------------------------
// attn helpers
// ---------------------------------------------------------------------------
__device__ __forceinline__ uint32_t smem_u32(const void* p) {
    uint32_t a;
    asm("{ .reg .u64 t; cvta.to.shared.u64 t, %1; cvt.u32.u64 %0, t; }" : "=r"(a) : "l"(p));
    return a;
}
__device__ __forceinline__ void cp_async16s(uint32_t dst, const void* src) {
    asm volatile("cp.async.cg.shared.global [%0], [%1], 16;" :: "r"(dst), "l"(src) : "memory");
}
__device__ __forceinline__ float ex2f(float x) {
    float r; asm("ex2.approx.ftz.f32 %0, %1;" : "=f"(r) : "f"(x)); return r;
}
#define MMAF16(c, a, b0, b1) \
    asm volatile("mma.sync.aligned.m16n8k16.row.col.f32.f16.f16.f32 " \
        "{%0,%1,%2,%3}, {%4,%5,%6,%7}, {%8,%9}, {%0,%1,%2,%3};" \
        : "+f"((c)[0]), "+f"((c)[1]), "+f"((c)[2]), "+f"((c)[3]) \
        : "r"((a)[0]), "r"((a)[1]), "r"((a)[2]), "r"((a)[3]), "r"(b0), "r"(b1))

#define B_ROWSTR 160
#define B_BUF    (128 * B_ROWSTR)          // 20480 B
#define B_NBUF   3

// ---------------------------------------------------------------------------
// attn: per warp 32 rows (2 m16 blocks; A fp16 resident in regs).
// 3-buffer cp.async pipeline -> ONE __syncthreads per tile.
// grid (16 rowtiles, 8 bb) = 128 CTAs, 256 thr, smem 61440B, 1 wave.
// ---------------------------------------------------------------------------
__global__ __launch_bounds__(256, 1) void attn_kernel()
{
    extern __shared__ char rawsm[];
    const uint32_t base = smem_u32(rawsm);
    const int tid = threadIdx.x;
    const int wid = tid >> 5, lane = tid & 31;
    const int g = lane >> 2, t = lane & 3;
    const int rowtile = blockIdx.x, bb = blockIdx.y;
    const int rbase = rowtile * 256;
    const __half* SH = g_s_h + (size_t)bb * N_SP * N_C;
    const uint8_t* FF = g_f_fused + (size_t)bb * N_SP * 128;

    uint32_t aH[2][4][4];
    {
        const int r0 = rbase + 32 * wid + g;
        #pragma unroll
        for (int rb = 0; rb < 2; ++rb) {
            const int ra = r0 + 16 * rb, rbot = ra + 8;
            #pragma unroll
            for (int kb = 0; kb < 4; ++kb) {
                const int k0 = 16 * kb + 2 * t;
                aH[rb][kb][0] = *(const uint32_t*)&SH[(size_t)ra * N_C + k0];
                aH[rb][kb][1] = *(const uint32_t*)&SH[(size_t)rbot * N_C + k0];
                aH[rb][kb][2] = *(const uint32_t*)&SH[(size_t)ra * N_C + k0 + 8];
                aH[rb][kb][3] = *(const uint32_t*)&SH[(size_t)rbot * N_C + k0 + 8];
            }
        }
    }

    // prologue: load tiles 0 and 1 into buffers 0,1
    #pragma unroll
    for (int p = 0; p < 2; ++p) {
        #pragma unroll
        for (int i = 0; i < 4; ++i) {
            int ci = tid + i * 256;
            int row = ci >> 3, ch = ci & 7;
            cp_async16s(base + p * B_BUF + row * B_ROWSTR + ch * 16,
                        FF + (size_t)(p * 128 + row) * 128 + ch * 16);
        }
        asm volatile("cp.async.commit_group;" ::: "memory");
    }

    float e00 = 0.f, e01 = 0.f, e10 = 0.f, e11 = 0.f;
    int bufj = 0;                       // j % 3
    for (int j = 0; j < 32; ++j) {
        asm volatile("cp.async.wait_group 1;" ::: "memory");
        __syncthreads();                // tile j visible; buffer j-1 released

        if (j + 2 < 32) {
            int buf2 = bufj + 2; if (buf2 >= 3) buf2 -= 3;
            const int cb = (j + 2) * 128;
            #pragma unroll
            for (int i = 0; i < 4; ++i) {
                int ci = tid + i * 256;
                int row = ci >> 3, ch = ci & 7;
                cp_async16s(base + buf2 * B_BUF + row * B_ROWSTR + ch * 16,
                            FF + (size_t)(cb + row) * 128 + ch * 16);
            }
            asm volatile("cp.async.commit_group;" ::: "memory");
        }

        const char* buf = rawsm + bufj * B_BUF;

        #pragma unroll 2
        for (int nt = 0; nt < 16; ++nt) {
            const char* rowp = buf + (nt * 8 + g) * B_ROWSTR + t * 8;
            uint2 bv[4];
            #pragma unroll
            for (int kb = 0; kb < 4; ++kb)
                bv[kb] = *(const uint2*)(rowp + kb * 32);

            float cA0[4] = {0.f,0.f,0.f,0.f};
            float cA1[4] = {0.f,0.f,0.f,0.f};
            #pragma unroll
            for (int kb = 0; kb < 4; ++kb) {
                MMAF16(cA0, aH[0][kb], bv[kb].x, bv[kb].y);
                MMAF16(cA1, aH[1][kb], bv[kb].x, bv[kb].y);
            }
            e00 += ex2f(cA0[0]) + ex2f(cA0[1]);
            e01 += ex2f(cA0[2]) + ex2f(cA0[3]);
            e10 += ex2f(cA1[0]) + ex2f(cA1[1]);
            e11 += ex2f(cA1[2]) + ex2f(cA1[3]);
        }

        if (++bufj == 3) bufj = 0;
    }

    #pragma unroll
    for (int off = 1; off < 4; off <<= 1) {
        e00 += __shfl_xor_sync(0xffffffffu, e00, off);
        e01 += __shfl_xor_sync(0xffffffffu, e01, off);
        e10 += __shfl_xor_sync(0xffffffffu, e10, off);
        e11 += __shfl_xor_sync(0xffffffffu, e11, off);
    }
    if (t == 0) {
        const int rb0 = bb * N_SP + rbase + 32 * wid + g;
        g_rowE[rb0]      = e00;
        g_rowE[rb0 + 8]  = e01;
        g_rowE[rb0 + 16] = e10;
        g_rowE[rb0 + 24] = e11;
    }
}

// ---------------------------------------------------------------------------
// qdot: one CTA per (bb,c): q = (sum_n g[c,n]*E_n) / (sum_n E_n). grid 512.
// g read as fp16 (uint4 = 8 values). Also folds the 32 sumx partials.
// ---------------------------------------------------------------------------
__global__ __launch_bounds__(128) void qdot_kernel()
{
    __shared__ float redP[4], redZ[4];
    const int tid = threadIdx.x;
    const int blk = blockIdx.x;
    const int bb = blk >> 6, c = blk & 63;

    if (tid < 32) {
        float s = g_sumx_part[(bb * 32 + tid) * N_C + c];
        #pragma unroll
        for (int off = 16; off > 0; off >>= 1)
            s += __shfl_xor_sync(0xffffffffu, s, off);
        if (tid == 0) g_sumx[bb * N_C + c] = s;
    }

    const uint4* gph = (const uint4*)(g_g_h + (size_t)bb * N_C * N_SP + (size_t)c * N_SP);
    const float4* ep = (const float4*)(g_rowE + bb * N_SP);
    float p = 0.f, z = 0.f;
    #pragma unroll 2
    for (int i = tid; i < 512; i += 128) {
        uint4 gv = gph[i];
        float4 e0 = ep[2 * i], e1 = ep[2 * i + 1];
        float2 ga = __half22float2(*(const __half2*)&gv.x);
        float2 gb = __half22float2(*(const __half2*)&gv.y);
        float2 gc = __half22float2(*(const __half2*)&gv.z);
        float2 gd = __half22float2(*(const __half2*)&gv.w);
        p = fmaf(ga.x, e0.x, p); p = fmaf(ga.y, e0.y, p);
        p = fmaf(gb.x, e0.z, p); p = fmaf(gb.y, e0.w, p);
        p = fmaf(gc.x, e1.x, p); p = fmaf(gc.y, e1.y, p);
        p = fmaf(gd.x, e1.z, p); p = fmaf(gd.y, e1.w, p);
        z += (e0.x + e0.y) + (e0.z + e0.w) + (e1.x + e1.y) + (e1.z + e1.w);
    }
    #pragma unroll
    for (int off = 16; off > 0; off >>= 1) {
        p += __shfl_xor_sync(0xffffffffu, p, off);
        z += __shfl_xor_sync(0xffffffffu, z, off);
    }
    if ((tid & 31) == 0) { redP[tid >> 5] = p; redZ[tid >> 5] = z; }
    __syncthreads();
    if (tid == 0) {
        float P = redP[0] + redP[1] + redP[2] + redP[3];
        float Z = redZ[0] + redZ[1] + redZ[2] + redZ[3];
        g_q[bb * 64 + c] = P / Z;
    }
}

// ---------------------------------------------------------------------------
// loss: cooperative smem preload, dots from smem (R13-validated).
// ---------------------------------------------------------------------------
__global__ __launch_bounds__(256) void loss_kernel(const float* __restrict__ fsg_w,
                                                   const float* __restrict__ fsg_b,
                                                   float* __restrict__ out, int out_size)
{
    __shared__ float sQ[512];
    __shared__ float sSX[512];
    __shared__ float sWt[64 * 65];     // sWt[c*65+d] = fsg_w[d*64+c]
    __shared__ float red[256];
    const int tid = threadIdx.x;

    #pragma unroll
    for (int i = tid; i < 512; i += 256) {
        sQ[i]  = g_q[i];
        sSX[i] = g_sumx[i];
    }
    #pragma unroll
    for (int i = tid; i < 4096; i += 256) {
        int d = i >> 6, c = i & 63;
        sWt[c * 65 + d] = fsg_w[i];
    }
    __syncthreads();

    const int b = tid >> 6, d = tid & 63;
    float dot_s = 0.f, dot_t = 0.f;
    #pragma unroll 8
    for (int c = 0; c < 64; ++c) {
        float w = sWt[c * 65 + d];
        dot_s = fmaf(w, sQ[b * 64 + c], dot_s);
        dot_t = fmaf(w, sQ[(4 + b) * 64 + c], dot_t);
    }
    const float invN = 1.f / 4096.f;
    float out_s = sSX[b * 64 + d] * invN + dot_s * invN + fsg_b[d];
    float out_t = sSX[(4 + b) * 64 + d] * invN + dot_t * invN + fsg_b[d];
    float diff = out_s - out_t;
    red[tid] = diff * diff;
    __syncthreads();
    for (int off = 128; off > 0; off >>= 1) {
        if (tid < off) red[tid] += red[tid + off];
        __syncthreads();
    }
    const float nlB = 0.05f * 4e-4f * red[0];        // non_loss * B
    for (int i = tid; i < out_size; i += 256)
        out[i] = (i == 0) ? nlB : nlB * 0.25f;       // [non_loss*B, non_loss]
}

// ---------------------------------------------------------------------------
extern "C" void kernel_launch(void* const* d_in, const int* in_sizes, int n_in,
                              void* d_out, int out_size)
{
    (void)in_sizes; (void)n_in;
    const float* student = (const float*)d_in[0];
    const float* teacher = (const float*)d_in[1];
    const float* si_w  = (const float*)d_in[2];
    const float* si_b  = (const float*)d_in[3];
    const float* fi_w  = (const float*)d_in[4];
    const float* fi_b  = (const float*)d_in[5];
    const float* gi_w  = (const float*)d_in[6];
    const float* gi_b  = (const float*)d_in[7];
    const float* fsg_w = (const float*)d_in[8];
    const float* fsg_b = (const float*)d_in[9];

    cudaFuncSetAttribute(prep_kernel, cudaFuncAttributeMaxDynamicSharedMemorySize, PREP_SMEM);
    cudaFuncSetAttribute(attn_kernel, cudaFuncAttributeMaxDynamicSharedMemorySize, B_NBUF * B_BUF);

    prep_kernel<<<dim3(32, 8), 256, PREP_SMEM>>>(student, teacher, si_w, si_b, fi_w, fi_b, gi_w, gi_b);
    attn_kernel<<<dim3(16, 8), 256, B_NBUF * B_BUF>>>();
    qdot_kernel<<<512, 128>>>();
    loss_kernel<<<1, 256>>>(fsg_w, fsg_b, (float*)d_out, out_size);
}